// round 2
// baseline (speedup 1.0000x reference)
#include <cuda_runtime.h>

#define NMAX 100000
#define Dd 100
#define KK 200
#define TILE 128
#define NTHREADS 256

// Scratch (no allocations allowed): agg sums, hidden features, reciprocal degree.
__device__ float g_agg[(size_t)NMAX * Dd];
__device__ float g_feat[(size_t)NMAX * Dd];
__device__ float g_rdeg[NMAX];

// One warp per edge: lanes 0..24 move one float4 of the 100-float row via
// vector reduction atomics (red.global.add.v4.f32). Lane 25 optionally counts degree.
__global__ void agg_kernel(const float* __restrict__ xin,
                           const int* __restrict__ src,
                           const int* __restrict__ dst,
                           float* __restrict__ agg,
                           float* deg, int nE)
{
    int w = (blockIdx.x * blockDim.x + threadIdx.x) >> 5;
    int lane = threadIdx.x & 31;
    if (w >= nE) return;
    int s = __ldg(src + w);
    int d = __ldg(dst + w);
    if (lane < 25) {
        const float4 v = __ldg(reinterpret_cast<const float4*>(xin + (size_t)s * Dd) + lane);
        float* a = agg + (size_t)d * Dd + lane * 4;
        asm volatile("red.global.add.v4.f32 [%0], {%1,%2,%3,%4};"
                     :: "l"(a), "f"(v.x), "f"(v.y), "f"(v.z), "f"(v.w)
                     : "memory");
    } else if (lane == 25 && deg != nullptr) {
        atomicAdd(deg + d, 1.0f);
    }
}

__global__ void rdeg_kernel(float* deg, int n) {
    int i = blockIdx.x * blockDim.x + threadIdx.x;
    if (i < n) deg[i] = 1.0f / fmaxf(deg[i], 1.0f);
}

// out[i,:] = (agg[i,:]*rdeg[i]) @ Wa + root[i,:] @ Wr + b   (optional ReLU)
// Treated as a single GEMM with K=200: A = [agg*rdeg | root], W = [Wa ; Wr].
// Block: 128 nodes x 100 cols, 256 threads, 16x4 micro-tile per thread.
// W (200x100, 80KB) and the A tile (128x200, 102.4KB) both live in dynamic smem.
__global__ void layer_kernel(const float* __restrict__ agg,
                             const float* __restrict__ rdeg,
                             const float* __restrict__ root,
                             const float* __restrict__ Wa,
                             const float* __restrict__ Wr,
                             const float* __restrict__ bias,
                             float* __restrict__ out,
                             int n, int doRelu)
{
    extern __shared__ float sm[];
    float* Ws = sm;             // [KK][Dd]
    float* As = sm + KK * Dd;   // [TILE][KK]
    int tid = threadIdx.x;
    int base = blockIdx.x * TILE;

    for (int idx = tid; idx < KK * Dd; idx += NTHREADS)
        Ws[idx] = (idx < Dd * Dd) ? Wa[idx] : Wr[idx - Dd * Dd];

    for (int idx = tid; idx < TILE * KK; idx += NTHREADS) {
        int r = idx / KK, k = idx - r * KK;
        int node = base + r;
        float v = 0.f;
        if (node < n)
            v = (k < Dd) ? agg[(size_t)node * Dd + k] * rdeg[node]
                         : root[(size_t)node * Dd + (k - Dd)];
        As[idx] = v;
    }
    __syncthreads();

    int tx = tid & 31, ty = tid >> 5;   // ty in 0..7
    float acc[16][4];
    #pragma unroll
    for (int i = 0; i < 16; i++)
        acc[i][0] = acc[i][1] = acc[i][2] = acc[i][3] = 0.f;

    #pragma unroll 2
    for (int k = 0; k < KK; k++) {
        float w0 = Ws[k * Dd + tx];
        float w1 = Ws[k * Dd + tx + 32];
        float w2 = Ws[k * Dd + tx + 64];
        float w3 = (tx < 4) ? Ws[k * Dd + tx + 96] : 0.f;
        #pragma unroll
        for (int nn = 0; nn < 16; nn++) {
            float a = As[(ty + 8 * nn) * KK + k];
            acc[nn][0] += a * w0;
            acc[nn][1] += a * w1;
            acc[nn][2] += a * w2;
            acc[nn][3] += a * w3;
        }
    }

    float b0 = __ldg(bias + tx);
    float b1 = __ldg(bias + tx + 32);
    float b2 = __ldg(bias + tx + 64);
    float b3 = (tx < 4) ? __ldg(bias + tx + 96) : 0.f;

    #pragma unroll
    for (int nn = 0; nn < 16; nn++) {
        int node = base + ty + 8 * nn;
        if (node >= n) continue;
        float o0 = acc[nn][0] + b0;
        float o1 = acc[nn][1] + b1;
        float o2 = acc[nn][2] + b2;
        float o3 = acc[nn][3] + b3;
        if (doRelu) {
            o0 = fmaxf(o0, 0.f); o1 = fmaxf(o1, 0.f);
            o2 = fmaxf(o2, 0.f); o3 = fmaxf(o3, 0.f);
        }
        float* orow = out + (size_t)node * Dd;
        orow[tx]      = o0;
        orow[tx + 32] = o1;
        orow[tx + 64] = o2;
        if (tx < 4) orow[tx + 96] = o3;
    }
}

extern "C" void kernel_launch(void* const* d_in, const int* in_sizes, int n_in,
                              void* d_out, int out_size)
{
    const float* x   = (const float*)d_in[0];
    const int*   ei  = (const int*)d_in[1];
    // d_in[2] = edge_weight (unused by the reference)
    const float* Wsa = (const float*)d_in[3];
    const float* Wsr = (const float*)d_in[4];
    const float* bs  = (const float*)d_in[5];
    const float* Wma = (const float*)d_in[6];
    const float* Wmr = (const float*)d_in[7];
    const float* bm  = (const float*)d_in[8];
    const float* Wva = (const float*)d_in[9];
    const float* Wvr = (const float*)d_in[10];
    const float* bv  = (const float*)d_in[11];

    int n  = in_sizes[0] / Dd;
    int nE = in_sizes[1] / 2;
    const int* src = ei;
    const int* dstp = ei + nE;

    float *agg, *feat, *rdeg;
    cudaGetSymbolAddress((void**)&agg,  g_agg);
    cudaGetSymbolAddress((void**)&feat, g_feat);
    cudaGetSymbolAddress((void**)&rdeg, g_rdeg);

    size_t smem = (size_t)(KK * Dd + TILE * KK) * sizeof(float);
    cudaFuncSetAttribute(layer_kernel,
                         cudaFuncAttributeMaxDynamicSharedMemorySize, (int)smem);

    cudaMemsetAsync(agg,  0, (size_t)n * Dd * sizeof(float));
    cudaMemsetAsync(rdeg, 0, (size_t)n * sizeof(float));

    int aggBlocks = (nE + 7) / 8;   // 8 warps (edges) per 256-thread block
    agg_kernel<<<aggBlocks, 256>>>(x, src, dstp, agg, rdeg, nE);
    rdeg_kernel<<<(n + 255) / 256, 256>>>(rdeg, n);

    int layerBlocks = (n + TILE - 1) / TILE;
    layer_kernel<<<layerBlocks, NTHREADS, smem>>>(agg, rdeg, x, Wsa, Wsr, bs,
                                                  feat, n, 1);

    cudaMemsetAsync(agg, 0, (size_t)n * Dd * sizeof(float));
    agg_kernel<<<aggBlocks, 256>>>(feat, src, dstp, agg, nullptr, nE);

    float* outp = (float*)d_out;
    layer_kernel<<<layerBlocks, NTHREADS, smem>>>(agg, rdeg, feat, Wma, Wmr, bm,
                                                  outp, n, 0);
    layer_kernel<<<layerBlocks, NTHREADS, smem>>>(agg, rdeg, feat, Wva, Wvr, bv,
                                                  outp + (size_t)n * Dd, n, 0);
}

// round 3
// speedup vs baseline: 1.2719x; 1.2719x over previous
#include <cuda_runtime.h>

#define NMAX 100000
#define Dd 100
#define KK 200
#define KT 20
#define TILE 128
#define NTHREADS 256

__device__ float g_agg[(size_t)NMAX * Dd];
__device__ float g_feat[(size_t)NMAX * Dd];
__device__ float g_rdeg[NMAX];

// Degree count: one thread per edge, fire-and-forget reduction.
__global__ void deg_kernel(const int* __restrict__ dst, float* deg, int nE) {
    int e = blockIdx.x * blockDim.x + threadIdx.x;
    if (e >= nE) return;
    int d = __ldg(dst + e);
    asm volatile("red.global.add.f32 [%0], %1;" :: "l"(deg + d), "f"(1.0f) : "memory");
}

__global__ void rdeg_kernel(float* deg, int n) {
    int i = blockIdx.x * blockDim.x + threadIdx.x;
    if (i < n) deg[i] = 1.0f / fmaxf(deg[i], 1.0f);
}

// One thread per (edge, float4-chunk): 25 chunks cover the 100-float row.
__global__ void agg_kernel(const float* __restrict__ xin,
                           const int* __restrict__ src,
                           const int* __restrict__ dst,
                           float* __restrict__ agg, int nE)
{
    int tid = blockIdx.x * blockDim.x + threadIdx.x;
    int e = tid / 25;
    if (e >= nE) return;
    int q = tid - e * 25;
    int s = __ldg(src + e);
    int d = __ldg(dst + e);
    float4 v = __ldg(reinterpret_cast<const float4*>(xin + (size_t)s * Dd) + q);
    float* a = agg + (size_t)d * Dd + q * 4;
    asm volatile("red.global.add.v4.f32 [%0], {%1,%2,%3,%4};"
                 :: "l"(a), "f"(v.x), "f"(v.y), "f"(v.z), "f"(v.w)
                 : "memory");
}

// out[i,:] = (agg[i,:]*rdeg[i]) @ Wa + root[i,:] @ Wr + b   (optional ReLU)
// W (200x100 = 80KB) resident in smem; A streamed in double-buffered k-tiles
// of 20 (2 x 10.24KB). Total smem ~100.5KB -> 2 CTAs/SM, 4 warps/SMSP.
__global__ void __launch_bounds__(NTHREADS, 2)
layer_kernel(const float* __restrict__ agg,
             const float* __restrict__ rdeg,
             const float* __restrict__ root,
             const float* __restrict__ Wa,
             const float* __restrict__ Wr,
             const float* __restrict__ bias,
             float* __restrict__ out,
             int n, int doRelu)
{
    extern __shared__ float sm[];
    float* Ws = sm;                  // [KK][Dd]  80000 B
    float* As = sm + KK * Dd;        // 2 x [TILE][KT]
    const int tid = threadIdx.x;
    const int base = blockIdx.x * TILE;

    // Stage W = [Wa ; Wr] (float4 vectorized: 5000 float4s)
    {
        const float4* wa4 = reinterpret_cast<const float4*>(Wa);
        const float4* wr4 = reinterpret_cast<const float4*>(Wr);
        float4* ws4 = reinterpret_cast<float4*>(Ws);
        for (int idx = tid; idx < (KK * Dd) / 4; idx += NTHREADS)
            ws4[idx] = (idx < (Dd * Dd) / 4) ? __ldg(wa4 + idx)
                                             : __ldg(wr4 + idx - (Dd * Dd) / 4);
    }

    // Staging lambda: tile t covers k in [t*KT, t*KT+KT)
    auto stage = [&](int t) {
        float* dstb = As + (t & 1) * (TILE * KT);
        int k0 = t * KT;
        for (int idx = tid; idx < TILE * (KT / 4); idx += NTHREADS) {
            int r = idx / (KT / 4);
            int q = idx - r * (KT / 4);
            int node = base + r;
            float4 v = make_float4(0.f, 0.f, 0.f, 0.f);
            if (node < n) {
                if (k0 < Dd) {
                    v = __ldg(reinterpret_cast<const float4*>(
                            agg + (size_t)node * Dd + k0) + q);
                    float rd = __ldg(rdeg + node);
                    v.x *= rd; v.y *= rd; v.z *= rd; v.w *= rd;
                } else {
                    v = __ldg(reinterpret_cast<const float4*>(
                            root + (size_t)node * Dd + (k0 - Dd)) + q);
                }
            }
            reinterpret_cast<float4*>(dstb + r * KT)[q] = v;
        }
    };

    stage(0);
    __syncthreads();

    const int tx = tid & 31, ty = tid >> 5;    // ty in 0..7
    float acc[16][4];
    #pragma unroll
    for (int i = 0; i < 16; i++)
        acc[i][0] = acc[i][1] = acc[i][2] = acc[i][3] = 0.f;

    const int NTILES = KK / KT;   // 10
    for (int t = 0; t < NTILES; t++) {
        if (t + 1 < NTILES) stage(t + 1);
        const float* buf = As + (t & 1) * (TILE * KT);
        int k0 = t * KT;
        #pragma unroll
        for (int kk = 0; kk < KT; kk++) {
            const float* wrow = Ws + (k0 + kk) * Dd;
            float w0 = wrow[tx];
            float w1 = wrow[tx + 32];
            float w2 = wrow[tx + 64];
            float w3 = (tx < 4) ? wrow[tx + 96] : 0.f;
            #pragma unroll
            for (int nn = 0; nn < 16; nn++) {
                float a = buf[(ty + 8 * nn) * KT + kk];
                acc[nn][0] += a * w0;
                acc[nn][1] += a * w1;
                acc[nn][2] += a * w2;
                acc[nn][3] += a * w3;
            }
        }
        __syncthreads();
    }

    float b0 = __ldg(bias + tx);
    float b1 = __ldg(bias + tx + 32);
    float b2 = __ldg(bias + tx + 64);
    float b3 = (tx < 4) ? __ldg(bias + tx + 96) : 0.f;

    #pragma unroll
    for (int nn = 0; nn < 16; nn++) {
        int node = base + ty + 8 * nn;
        if (node >= n) continue;
        float o0 = acc[nn][0] + b0;
        float o1 = acc[nn][1] + b1;
        float o2 = acc[nn][2] + b2;
        float o3 = acc[nn][3] + b3;
        if (doRelu) {
            o0 = fmaxf(o0, 0.f); o1 = fmaxf(o1, 0.f);
            o2 = fmaxf(o2, 0.f); o3 = fmaxf(o3, 0.f);
        }
        float* orow = out + (size_t)node * Dd;
        orow[tx]      = o0;
        orow[tx + 32] = o1;
        orow[tx + 64] = o2;
        if (tx < 4) orow[tx + 96] = o3;
    }
}

extern "C" void kernel_launch(void* const* d_in, const int* in_sizes, int n_in,
                              void* d_out, int out_size)
{
    const float* x   = (const float*)d_in[0];
    const int*   ei  = (const int*)d_in[1];
    const float* Wsa = (const float*)d_in[3];
    const float* Wsr = (const float*)d_in[4];
    const float* bs  = (const float*)d_in[5];
    const float* Wma = (const float*)d_in[6];
    const float* Wmr = (const float*)d_in[7];
    const float* bm  = (const float*)d_in[8];
    const float* Wva = (const float*)d_in[9];
    const float* Wvr = (const float*)d_in[10];
    const float* bv  = (const float*)d_in[11];

    int n  = in_sizes[0] / Dd;
    int nE = in_sizes[1] / 2;
    const int* src  = ei;
    const int* dstp = ei + nE;

    float *agg, *feat, *rdeg;
    cudaGetSymbolAddress((void**)&agg,  g_agg);
    cudaGetSymbolAddress((void**)&feat, g_feat);
    cudaGetSymbolAddress((void**)&rdeg, g_rdeg);

    size_t smem = (size_t)(KK * Dd + 2 * TILE * KT) * sizeof(float);
    static bool attrSet = false;
    if (!attrSet) {
        cudaFuncSetAttribute(layer_kernel,
                             cudaFuncAttributeMaxDynamicSharedMemorySize, (int)smem);
        attrSet = true;
    }

    cudaMemsetAsync(agg,  0, (size_t)n * Dd * sizeof(float));
    cudaMemsetAsync(rdeg, 0, (size_t)n * sizeof(float));

    deg_kernel<<<(nE + 255) / 256, 256>>>(dstp, rdeg, nE);
    rdeg_kernel<<<(n + 255) / 256, 256>>>(rdeg, n);

    int aggThreads = nE * 25;
    int aggBlocks  = (aggThreads + 255) / 256;
    agg_kernel<<<aggBlocks, 256>>>(x, src, dstp, agg, nE);

    int layerBlocks = (n + TILE - 1) / TILE;
    layer_kernel<<<layerBlocks, NTHREADS, smem>>>(agg, rdeg, x, Wsa, Wsr, bs,
                                                  feat, n, 1);

    cudaMemsetAsync(agg, 0, (size_t)n * Dd * sizeof(float));
    agg_kernel<<<aggBlocks, 256>>>(feat, src, dstp, agg, nE);

    float* outp = (float*)d_out;
    layer_kernel<<<layerBlocks, NTHREADS, smem>>>(agg, rdeg, feat, Wma, Wmr, bm,
                                                  outp, n, 0);
    layer_kernel<<<layerBlocks, NTHREADS, smem>>>(agg, rdeg, feat, Wva, Wvr, bv,
                                                  outp + (size_t)n * Dd, n, 0);
}

// round 4
// speedup vs baseline: 1.5219x; 1.1966x over previous
#include <cuda_runtime.h>

#define NMAX 100000
#define Dd 100
#define KK 200
#define NTHREADS 256

__device__ float g_agg[(size_t)NMAX * Dd];
__device__ float g_feat[(size_t)NMAX * Dd];
__device__ float g_rdeg[NMAX];

__global__ void rdeg_kernel(float* deg, int n) {
    int i = blockIdx.x * blockDim.x + threadIdx.x;
    if (i < n) deg[i] = 1.0f / fmaxf(deg[i], 1.0f);
}

// One thread per edge: coalesced src/dst loads, 25 float4 gather+reduce pairs.
__global__ void agg_kernel(const float* __restrict__ xin,
                           const int* __restrict__ src,
                           const int* __restrict__ dst,
                           float* __restrict__ agg,
                           float* deg, int nE)
{
    int e = blockIdx.x * blockDim.x + threadIdx.x;
    if (e >= nE) return;
    int s = __ldg(src + e);
    int d = __ldg(dst + e);
    if (deg != nullptr)
        asm volatile("red.global.add.f32 [%0], %1;"
                     :: "l"(deg + d), "f"(1.0f) : "memory");
    const float4* xs = reinterpret_cast<const float4*>(xin + (size_t)s * Dd);
    float* ab = agg + (size_t)d * Dd;
    #pragma unroll 5
    for (int q = 0; q < 25; q++) {
        float4 v = __ldg(xs + q);
        asm volatile("red.global.add.v4.f32 [%0], {%1,%2,%3,%4};"
                     :: "l"(ab + 4 * q), "f"(v.x), "f"(v.y), "f"(v.z), "f"(v.w)
                     : "memory");
    }
}

// Each thread owns one row and NF4 float4 output columns (held in registers).
// W is smem-resident and read via broadcast LDS.128. No A tile, no inner barriers.
template<int NF4>
__device__ __forceinline__ void compute_half(
    const float* __restrict__ Ws, const float* __restrict__ bs,
    const float* __restrict__ agg, const float* __restrict__ rdeg,
    const float* __restrict__ root, float* __restrict__ out,
    int r, int c0, int n, int doRelu)
{
    if (r >= n) return;
    float4 acc[NF4];
    #pragma unroll
    for (int c = 0; c < NF4; c++) acc[c] = make_float4(0.f, 0.f, 0.f, 0.f);

    const float rd = rdeg[r];
    const float4* ar = reinterpret_cast<const float4*>(agg + (size_t)r * Dd);
    const float4* rr = reinterpret_cast<const float4*>(root + (size_t)r * Dd);

    float4 a = __ldg(ar);
    // k = 0..99 : mean-aggregated neighborhood (scaled by rd)
    #pragma unroll 1
    for (int kt = 0; kt < 25; kt++) {
        float4 cur = a;
        a = (kt < 24) ? __ldg(ar + kt + 1) : __ldg(rr);
        cur.x *= rd; cur.y *= rd; cur.z *= rd; cur.w *= rd;
        const float* wbase = Ws + (kt * 4) * Dd + c0;
        #pragma unroll
        for (int kk = 0; kk < 4; kk++) {
            float av = (kk == 0) ? cur.x : (kk == 1) ? cur.y : (kk == 2) ? cur.z : cur.w;
            const float4* wrow = reinterpret_cast<const float4*>(wbase + kk * Dd);
            #pragma unroll
            for (int c = 0; c < NF4; c++) {
                float4 w = wrow[c];
                acc[c].x = fmaf(av, w.x, acc[c].x);
                acc[c].y = fmaf(av, w.y, acc[c].y);
                acc[c].z = fmaf(av, w.z, acc[c].z);
                acc[c].w = fmaf(av, w.w, acc[c].w);
            }
        }
    }
    // k = 100..199 : root features
    #pragma unroll 1
    for (int kt = 0; kt < 25; kt++) {
        float4 cur = a;
        if (kt < 24) a = __ldg(rr + kt + 1);
        const float* wbase = Ws + (100 + kt * 4) * Dd + c0;
        #pragma unroll
        for (int kk = 0; kk < 4; kk++) {
            float av = (kk == 0) ? cur.x : (kk == 1) ? cur.y : (kk == 2) ? cur.z : cur.w;
            const float4* wrow = reinterpret_cast<const float4*>(wbase + kk * Dd);
            #pragma unroll
            for (int c = 0; c < NF4; c++) {
                float4 w = wrow[c];
                acc[c].x = fmaf(av, w.x, acc[c].x);
                acc[c].y = fmaf(av, w.y, acc[c].y);
                acc[c].z = fmaf(av, w.z, acc[c].z);
                acc[c].w = fmaf(av, w.w, acc[c].w);
            }
        }
    }

    const float4* bf = reinterpret_cast<const float4*>(bs + c0);
    float4* orow = reinterpret_cast<float4*>(out + (size_t)r * Dd + c0);
    #pragma unroll
    for (int c = 0; c < NF4; c++) {
        float4 b = bf[c];
        float4 v;
        v.x = acc[c].x + b.x;
        v.y = acc[c].y + b.y;
        v.z = acc[c].z + b.z;
        v.w = acc[c].w + b.w;
        if (doRelu) {
            v.x = fmaxf(v.x, 0.f); v.y = fmaxf(v.y, 0.f);
            v.z = fmaxf(v.z, 0.f); v.w = fmaxf(v.w, 0.f);
        }
        orow[c] = v;
    }
}

// Block: 128 rows x 2 column-halves (threads 0..127 -> cols 0..51, 128..255 -> 52..99).
// gridDim.y selects weight set (used to fuse mu+var into one launch).
__global__ void __launch_bounds__(NTHREADS, 2)
layer_kernel(const float* __restrict__ agg,
             const float* __restrict__ rdeg,
             const float* __restrict__ root,
             const float* __restrict__ Wa0, const float* __restrict__ Wr0,
             const float* __restrict__ b0,
             const float* __restrict__ Wa1, const float* __restrict__ Wr1,
             const float* __restrict__ b1,
             float* __restrict__ out, int n, int doRelu)
{
    extern __shared__ float sm[];
    float* Ws = sm;               // [KK][Dd]  80000 B
    float* bs = sm + KK * Dd;     // [Dd]

    const float* Wa = blockIdx.y ? Wa1 : Wa0;
    const float* Wr = blockIdx.y ? Wr1 : Wr0;
    const float* bb = blockIdx.y ? b1 : b0;
    out += (size_t)blockIdx.y * n * Dd;

    const int tid = threadIdx.x;
    const float4* wa4 = reinterpret_cast<const float4*>(Wa);
    const float4* wr4 = reinterpret_cast<const float4*>(Wr);
    float4* ws4 = reinterpret_cast<float4*>(Ws);
    for (int i = tid; i < (KK * Dd) / 4; i += NTHREADS)
        ws4[i] = (i < (Dd * Dd) / 4) ? __ldg(wa4 + i)
                                     : __ldg(wr4 + i - (Dd * Dd) / 4);
    if (tid < Dd) bs[tid] = bb[tid];
    __syncthreads();

    int r = blockIdx.x * 128 + (tid & 127);
    if (tid < 128)
        compute_half<13>(Ws, bs, agg, rdeg, root, out, r, 0, n, doRelu);
    else
        compute_half<12>(Ws, bs, agg, rdeg, root, out, r, 52, n, doRelu);
}

extern "C" void kernel_launch(void* const* d_in, const int* in_sizes, int n_in,
                              void* d_out, int out_size)
{
    const float* x   = (const float*)d_in[0];
    const int*   ei  = (const int*)d_in[1];
    const float* Wsa = (const float*)d_in[3];
    const float* Wsr = (const float*)d_in[4];
    const float* bs_ = (const float*)d_in[5];
    const float* Wma = (const float*)d_in[6];
    const float* Wmr = (const float*)d_in[7];
    const float* bm  = (const float*)d_in[8];
    const float* Wva = (const float*)d_in[9];
    const float* Wvr = (const float*)d_in[10];
    const float* bv  = (const float*)d_in[11];

    int n  = in_sizes[0] / Dd;
    int nE = in_sizes[1] / 2;
    const int* src  = ei;
    const int* dstp = ei + nE;

    float *agg, *feat, *rdeg;
    cudaGetSymbolAddress((void**)&agg,  g_agg);
    cudaGetSymbolAddress((void**)&feat, g_feat);
    cudaGetSymbolAddress((void**)&rdeg, g_rdeg);

    size_t smem = (size_t)(KK * Dd + 128) * sizeof(float);
    static bool attrSet = false;
    if (!attrSet) {
        cudaFuncSetAttribute(layer_kernel,
                             cudaFuncAttributeMaxDynamicSharedMemorySize, (int)smem);
        attrSet = true;
    }

    cudaMemsetAsync(agg,  0, (size_t)n * Dd * sizeof(float));
    cudaMemsetAsync(rdeg, 0, (size_t)n * sizeof(float));

    int aggBlocks = (nE + 255) / 256;
    agg_kernel<<<aggBlocks, 256>>>(x, src, dstp, agg, rdeg, nE);
    rdeg_kernel<<<(n + 255) / 256, 256>>>(rdeg, n);

    int rowBlocks = (n + 127) / 128;
    layer_kernel<<<dim3(rowBlocks, 1), NTHREADS, smem>>>(
        agg, rdeg, x, Wsa, Wsr, bs_, Wsa, Wsr, bs_, feat, n, 1);

    cudaMemsetAsync(agg, 0, (size_t)n * Dd * sizeof(float));
    agg_kernel<<<aggBlocks, 256>>>(feat, src, dstp, agg, nullptr, nE);

    float* outp = (float*)d_out;
    layer_kernel<<<dim3(rowBlocks, 2), NTHREADS, smem>>>(
        agg, rdeg, feat, Wma, Wmr, bm, Wva, Wvr, bv, outp, n, 0);
}

// round 5
// speedup vs baseline: 2.5958x; 1.7056x over previous
#include <cuda_runtime.h>

#define NMAX 100000
#define EMAX 1700000
#define Dd 100
#define KK 200
#define NTHREADS 256
#define SCAN_B 1024

__device__ float g_agg[(size_t)NMAX * Dd];
__device__ float g_feat[(size_t)NMAX * Dd];
__device__ int   g_deg[NMAX];
__device__ int   g_off[NMAX + 1];
__device__ int   g_cur[NMAX];
__device__ int   g_csr[EMAX];
__device__ int   g_bsum[(NMAX + SCAN_B - 1) / SCAN_B];

// ---------------- CSR build: histogram -> scan -> scatter ----------------

__global__ void hist_kernel(const int* __restrict__ dst, int* deg, int nE) {
    int e = blockIdx.x * blockDim.x + threadIdx.x;
    if (e < nE) atomicAdd(deg + __ldg(dst + e), 1);
}

// Block-local inclusive scan; writes local inclusive into scanOut, block total into bsum.
__global__ void scanA_kernel(const int* __restrict__ deg, int* scanOut,
                             int* bsum, int n) {
    __shared__ int sm[SCAN_B];
    int i = blockIdx.x * SCAN_B + threadIdx.x;
    int v = (i < n) ? deg[i] : 0;
    sm[threadIdx.x] = v;
    __syncthreads();
    for (int o = 1; o < SCAN_B; o <<= 1) {
        int t = (threadIdx.x >= o) ? sm[threadIdx.x - o] : 0;
        __syncthreads();
        sm[threadIdx.x] += t;
        __syncthreads();
    }
    if (i < n) scanOut[i] = sm[threadIdx.x];
    if (threadIdx.x == SCAN_B - 1) bsum[blockIdx.x] = sm[SCAN_B - 1];
}

// One-warp exclusive scan of the block sums (~98 elements).
__global__ void scanB_kernel(int* bsum, int nb) {
    int lane = threadIdx.x;
    int carry = 0;
    for (int base = 0; base < nb; base += 32) {
        int i = base + lane;
        int orig = (i < nb) ? bsum[i] : 0;
        int v = orig;
        #pragma unroll
        for (int o = 1; o < 32; o <<= 1) {
            int t = __shfl_up_sync(0xffffffffu, v, o);
            if (lane >= o) v += t;
        }
        if (i < nb) bsum[i] = carry + (v - orig);   // exclusive
        carry += __shfl_sync(0xffffffffu, v, 31);
    }
}

// off[i+1] = global inclusive; cur[i] = global exclusive (= inclusive - deg[i]).
__global__ void scanC_kernel(const int* __restrict__ scanIn,
                             const int* __restrict__ bsum,
                             const int* __restrict__ deg,
                             int* off, int* cur, int n) {
    int i = blockIdx.x * SCAN_B + threadIdx.x;
    if (i < n) {
        int incl = scanIn[i] + bsum[blockIdx.x];
        off[i + 1] = incl;
        cur[i] = incl - deg[i];
    }
    if (i == 0) off[0] = 0;
}

__global__ void scatter_kernel(const int* __restrict__ src,
                               const int* __restrict__ dst,
                               int* cur, int* csr, int nE) {
    int e = blockIdx.x * blockDim.x + threadIdx.x;
    if (e >= nE) return;
    int pos = atomicAdd(cur + __ldg(dst + e), 1);
    csr[pos] = __ldg(src + e);
}

// ---------------- Gather aggregation: mean of neighbor rows ----------------
// One warp per destination node; lanes 0..24 own one float4 chunk of the row.
__global__ void gather_kernel(const float* __restrict__ xin,
                              const int* __restrict__ csr,
                              const int* __restrict__ off,
                              float* __restrict__ aggOut, int n)
{
    int node = blockIdx.x * 8 + (threadIdx.x >> 5);
    int lane = threadIdx.x & 31;
    if (node >= n) return;
    int s0 = __ldg(off + node), s1 = __ldg(off + node + 1);
    float4 acc = make_float4(0.f, 0.f, 0.f, 0.f);
    int j = s0;
    int idx = (j < s1) ? __ldg(csr + j) : 0;
    while (j < s1) {
        int nidx = (j + 1 < s1) ? __ldg(csr + j + 1) : 0;   // prefetch next index
        if (lane < 25) {
            float4 v = __ldg(reinterpret_cast<const float4*>(
                    xin + (size_t)idx * Dd) + lane);
            acc.x += v.x; acc.y += v.y; acc.z += v.z; acc.w += v.w;
        }
        idx = nidx;
        j++;
    }
    if (lane < 25) {
        float inv = (s1 > s0) ? 1.0f / (float)(s1 - s0) : 0.f;
        acc.x *= inv; acc.y *= inv; acc.z *= inv; acc.w *= inv;
        reinterpret_cast<float4*>(aggOut + (size_t)node * Dd)[lane] = acc;
    }
}

// ---------------- Dense layer: out = mean_agg @ Wa + root @ Wr + b ----------------
template<int NF4>
__device__ __forceinline__ void compute_half(
    const float* __restrict__ Ws, const float* __restrict__ bs,
    const float* __restrict__ agg, const float* __restrict__ root,
    float* __restrict__ out, int r, int c0, int n, int doRelu)
{
    if (r >= n) return;
    float4 acc[NF4];
    #pragma unroll
    for (int c = 0; c < NF4; c++) acc[c] = make_float4(0.f, 0.f, 0.f, 0.f);

    const float4* ar = reinterpret_cast<const float4*>(agg + (size_t)r * Dd);
    const float4* rr = reinterpret_cast<const float4*>(root + (size_t)r * Dd);

    float4 a = __ldg(ar);
    #pragma unroll 1
    for (int kt = 0; kt < 50; kt++) {
        float4 cur = a;
        a = (kt < 24) ? __ldg(ar + kt + 1)
          : (kt == 24) ? __ldg(rr)
          : (kt < 49) ? __ldg(rr + kt - 24) : a;
        const float* wbase = Ws + (kt * 4) * Dd + c0;
        #pragma unroll
        for (int kk = 0; kk < 4; kk++) {
            float av = (kk == 0) ? cur.x : (kk == 1) ? cur.y : (kk == 2) ? cur.z : cur.w;
            const float4* wrow = reinterpret_cast<const float4*>(wbase + kk * Dd);
            #pragma unroll
            for (int c = 0; c < NF4; c++) {
                float4 w = wrow[c];
                acc[c].x = fmaf(av, w.x, acc[c].x);
                acc[c].y = fmaf(av, w.y, acc[c].y);
                acc[c].z = fmaf(av, w.z, acc[c].z);
                acc[c].w = fmaf(av, w.w, acc[c].w);
            }
        }
    }

    const float4* bf = reinterpret_cast<const float4*>(bs + c0);
    float4* orow = reinterpret_cast<float4*>(out + (size_t)r * Dd + c0);
    #pragma unroll
    for (int c = 0; c < NF4; c++) {
        float4 b = bf[c];
        float4 v;
        v.x = acc[c].x + b.x;
        v.y = acc[c].y + b.y;
        v.z = acc[c].z + b.z;
        v.w = acc[c].w + b.w;
        if (doRelu) {
            v.x = fmaxf(v.x, 0.f); v.y = fmaxf(v.y, 0.f);
            v.z = fmaxf(v.z, 0.f); v.w = fmaxf(v.w, 0.f);
        }
        orow[c] = v;
    }
}

__global__ void __launch_bounds__(NTHREADS, 2)
layer_kernel(const float* __restrict__ agg,
             const float* __restrict__ root,
             const float* __restrict__ Wa0, const float* __restrict__ Wr0,
             const float* __restrict__ b0,
             const float* __restrict__ Wa1, const float* __restrict__ Wr1,
             const float* __restrict__ b1,
             float* __restrict__ out, int n, int doRelu)
{
    extern __shared__ float sm[];
    float* Ws = sm;               // [KK][Dd]  80000 B
    float* bs = sm + KK * Dd;

    const float* Wa = blockIdx.y ? Wa1 : Wa0;
    const float* Wr = blockIdx.y ? Wr1 : Wr0;
    const float* bb = blockIdx.y ? b1 : b0;
    out += (size_t)blockIdx.y * n * Dd;

    const int tid = threadIdx.x;
    const float4* wa4 = reinterpret_cast<const float4*>(Wa);
    const float4* wr4 = reinterpret_cast<const float4*>(Wr);
    float4* ws4 = reinterpret_cast<float4*>(Ws);
    for (int i = tid; i < (KK * Dd) / 4; i += NTHREADS)
        ws4[i] = (i < (Dd * Dd) / 4) ? __ldg(wa4 + i)
                                     : __ldg(wr4 + i - (Dd * Dd) / 4);
    if (tid < Dd) bs[tid] = bb[tid];
    __syncthreads();

    int r = blockIdx.x * 128 + (tid & 127);
    if (tid < 128)
        compute_half<13>(Ws, bs, agg, root, out, r, 0, n, doRelu);
    else
        compute_half<12>(Ws, bs, agg, root, out, r, 52, n, doRelu);
}

extern "C" void kernel_launch(void* const* d_in, const int* in_sizes, int n_in,
                              void* d_out, int out_size)
{
    const float* x   = (const float*)d_in[0];
    const int*   ei  = (const int*)d_in[1];
    const float* Wsa = (const float*)d_in[3];
    const float* Wsr = (const float*)d_in[4];
    const float* bs_ = (const float*)d_in[5];
    const float* Wma = (const float*)d_in[6];
    const float* Wmr = (const float*)d_in[7];
    const float* bm  = (const float*)d_in[8];
    const float* Wva = (const float*)d_in[9];
    const float* Wvr = (const float*)d_in[10];
    const float* bv  = (const float*)d_in[11];

    int n  = in_sizes[0] / Dd;
    int nE = in_sizes[1] / 2;
    const int* src  = ei;
    const int* dstp = ei + nE;

    float *agg, *feat;
    int *deg, *off, *cur, *csr, *bsum;
    cudaGetSymbolAddress((void**)&agg,  g_agg);
    cudaGetSymbolAddress((void**)&feat, g_feat);
    cudaGetSymbolAddress((void**)&deg,  g_deg);
    cudaGetSymbolAddress((void**)&off,  g_off);
    cudaGetSymbolAddress((void**)&cur,  g_cur);
    cudaGetSymbolAddress((void**)&csr,  g_csr);
    cudaGetSymbolAddress((void**)&bsum, g_bsum);

    size_t smem = (size_t)(KK * Dd + 128) * sizeof(float);
    static bool attrSet = false;
    if (!attrSet) {
        cudaFuncSetAttribute(layer_kernel,
                             cudaFuncAttributeMaxDynamicSharedMemorySize, (int)smem);
        attrSet = true;
    }

    // --- CSR build ---
    int nb = (n + SCAN_B - 1) / SCAN_B;
    cudaMemsetAsync(deg, 0, (size_t)n * sizeof(int));
    hist_kernel<<<(nE + 255) / 256, 256>>>(dstp, deg, nE);
    scanA_kernel<<<nb, SCAN_B>>>(deg, cur /*temp: local inclusive*/, bsum, n);
    scanB_kernel<<<1, 32>>>(bsum, nb);
    scanC_kernel<<<nb, SCAN_B>>>(cur, bsum, deg, off, cur, n);
    scatter_kernel<<<(nE + 255) / 256, 256>>>(src, dstp, cur, csr, nE);

    // --- Layer 1 ---
    int gatherBlocks = (n + 7) / 8;
    gather_kernel<<<gatherBlocks, 256>>>(x, csr, off, agg, n);

    int rowBlocks = (n + 127) / 128;
    layer_kernel<<<dim3(rowBlocks, 1), NTHREADS, smem>>>(
        agg, x, Wsa, Wsr, bs_, Wsa, Wsr, bs_, feat, n, 1);

    // --- Layers 2+3 (shared aggregation over feat) ---
    gather_kernel<<<gatherBlocks, 256>>>(feat, csr, off, agg, n);

    float* outp = (float*)d_out;
    layer_kernel<<<dim3(rowBlocks, 2), NTHREADS, smem>>>(
        agg, feat, Wma, Wmr, bm, Wva, Wvr, bv, outp, n, 0);
}

// round 6
// speedup vs baseline: 2.9698x; 1.1441x over previous
#include <cuda_runtime.h>
#include <cuda_bf16.h>
#include <cstdint>

#define NMAX 100000
#define EMAX 1700000
#define Dd 100
#define KDATA 200
#define NP 104            // padded output cols (13 x n8)
#define KP 216            // smem k-stride (208 data+pad, conflict-free for ldmatrix)
#define NTHREADS 256
#define SCAN_B 1024

__device__ float g_agg[(size_t)NMAX * Dd];
__device__ float g_feat[(size_t)NMAX * Dd];
__device__ int   g_deg[NMAX];
__device__ int   g_off[NMAX + 1];
__device__ int   g_cur[NMAX];
__device__ int   g_csr[EMAX];
__device__ int   g_bsum[(NMAX + SCAN_B - 1) / SCAN_B];
__device__ __nv_bfloat16 g_Bhi[3][NP * KP];   // [set][n*KP + k], k-contiguous
__device__ __nv_bfloat16 g_Blo[3][NP * KP];

// ---------------- CSR build: histogram -> scan -> scatter ----------------

__global__ void hist_kernel(const int* __restrict__ dst, int* deg, int nE) {
    int e = blockIdx.x * blockDim.x + threadIdx.x;
    if (e < nE) atomicAdd(deg + __ldg(dst + e), 1);
}

__global__ void scanA_kernel(const int* __restrict__ deg, int* scanOut,
                             int* bsum, int n) {
    __shared__ int sm[SCAN_B];
    int i = blockIdx.x * SCAN_B + threadIdx.x;
    int v = (i < n) ? deg[i] : 0;
    sm[threadIdx.x] = v;
    __syncthreads();
    for (int o = 1; o < SCAN_B; o <<= 1) {
        int t = (threadIdx.x >= o) ? sm[threadIdx.x - o] : 0;
        __syncthreads();
        sm[threadIdx.x] += t;
        __syncthreads();
    }
    if (i < n) scanOut[i] = sm[threadIdx.x];
    if (threadIdx.x == SCAN_B - 1) bsum[blockIdx.x] = sm[SCAN_B - 1];
}

__global__ void scanB_kernel(int* bsum, int nb) {
    int lane = threadIdx.x;
    int carry = 0;
    for (int base = 0; base < nb; base += 32) {
        int i = base + lane;
        int orig = (i < nb) ? bsum[i] : 0;
        int v = orig;
        #pragma unroll
        for (int o = 1; o < 32; o <<= 1) {
            int t = __shfl_up_sync(0xffffffffu, v, o);
            if (lane >= o) v += t;
        }
        if (i < nb) bsum[i] = carry + (v - orig);
        carry += __shfl_sync(0xffffffffu, v, 31);
    }
}

__global__ void scanC_kernel(const int* __restrict__ scanIn,
                             const int* __restrict__ bsum,
                             const int* __restrict__ deg,
                             int* off, int* cur, int n) {
    int i = blockIdx.x * SCAN_B + threadIdx.x;
    if (i < n) {
        int incl = scanIn[i] + bsum[blockIdx.x];
        off[i + 1] = incl;
        cur[i] = incl - deg[i];
    }
    if (i == 0) off[0] = 0;
}

__global__ void scatter_kernel(const int* __restrict__ src,
                               const int* __restrict__ dst,
                               int* cur, int* csr, int nE) {
    int e = blockIdx.x * blockDim.x + threadIdx.x;
    if (e >= nE) return;
    int pos = atomicAdd(cur + __ldg(dst + e), 1);
    csr[pos] = __ldg(src + e);
}

// ---------------- Gather aggregation: mean of neighbor rows ----------------

__global__ void gather_kernel(const float* __restrict__ xin,
                              const int* __restrict__ csr,
                              const int* __restrict__ off,
                              float* __restrict__ aggOut, int n)
{
    int node = blockIdx.x * 8 + (threadIdx.x >> 5);
    int lane = threadIdx.x & 31;
    if (node >= n) return;
    int s0 = __ldg(off + node), s1 = __ldg(off + node + 1);
    float4 acc = make_float4(0.f, 0.f, 0.f, 0.f);
    int j = s0;
    int idx = (j < s1) ? __ldg(csr + j) : 0;
    while (j < s1) {
        int nidx = (j + 1 < s1) ? __ldg(csr + j + 1) : 0;
        if (lane < 25) {
            float4 v = __ldg(reinterpret_cast<const float4*>(
                    xin + (size_t)idx * Dd) + lane);
            acc.x += v.x; acc.y += v.y; acc.z += v.z; acc.w += v.w;
        }
        idx = nidx;
        j++;
    }
    if (lane < 25) {
        float inv = (s1 > s0) ? 1.0f / (float)(s1 - s0) : 0.f;
        acc.x *= inv; acc.y *= inv; acc.z *= inv; acc.w *= inv;
        reinterpret_cast<float4*>(aggOut + (size_t)node * Dd)[lane] = acc;
    }
}

// ---------------- Weight prep: fp32 W -> padded, transposed bf16 hi/lo ----------------
// g_B*[set][n*KP + k] = Wcat[k][n], Wcat = [Wa ; Wr] (200 x 100), zero-padded.
__global__ void prep_kernel(const float* __restrict__ Wsa, const float* __restrict__ Wsr,
                            const float* __restrict__ Wma, const float* __restrict__ Wmr,
                            const float* __restrict__ Wva, const float* __restrict__ Wvr)
{
    int i = blockIdx.x * blockDim.x + threadIdx.x;
    if (i >= 3 * NP * KP) return;
    int s = i / (NP * KP);
    int rem = i - s * (NP * KP);
    int nIdx = rem / KP;
    int k = rem - nIdx * KP;
    const float* Wa = (s == 0) ? Wsa : (s == 1) ? Wma : Wva;
    const float* Wr = (s == 0) ? Wsr : (s == 1) ? Wmr : Wvr;
    float v = 0.f;
    if (nIdx < Dd && k < KDATA)
        v = (k < Dd) ? __ldg(Wa + k * Dd + nIdx) : __ldg(Wr + (k - Dd) * Dd + nIdx);
    __nv_bfloat16 h = __float2bfloat16(v);
    __nv_bfloat16 l = __float2bfloat16(v - __bfloat162float(h));
    g_Bhi[s][rem] = h;
    g_Blo[s][rem] = l;
}

// ---------------- Tensor-core layer: out = [agg|root] @ Wcat + b ----------------
// CTA: 128 rows x 104 cols. 8 warps, warp w does rows [16w, 16w+16).
// 3 passes: Ahi*Bhi + Ahi*Blo + Alo*Bhi into the same fp32 accumulators.
__global__ void __launch_bounds__(NTHREADS)
layer_mma(const float* __restrict__ agg, const float* __restrict__ root,
          const __nv_bfloat16* __restrict__ Bhi0, const __nv_bfloat16* __restrict__ Blo0,
          const float* __restrict__ bias0,
          const __nv_bfloat16* __restrict__ Bhi1, const __nv_bfloat16* __restrict__ Blo1,
          const float* __restrict__ bias1,
          float* __restrict__ out, int n, int doRelu)
{
    extern __shared__ char smraw[];
    float* sbias = reinterpret_cast<float*>(smraw);                    // 104 floats
    __nv_bfloat16* sA = reinterpret_cast<__nv_bfloat16*>(smraw + 512);
    __nv_bfloat16* Ahi = sA;
    __nv_bfloat16* Alo = Ahi + 128 * KP;
    __nv_bfloat16* Bhi = Alo + 128 * KP;
    __nv_bfloat16* Blo = Bhi + NP * KP;

    const __nv_bfloat16* gBhi = blockIdx.y ? Bhi1 : Bhi0;
    const __nv_bfloat16* gBlo = blockIdx.y ? Blo1 : Blo0;
    const float* gb = blockIdx.y ? bias1 : bias0;
    out += (size_t)blockIdx.y * n * Dd;

    const int tid = threadIdx.x;
    const int base = blockIdx.x * 128;

    // Stage B (bf16, already padded/transposed): 2808 float4 per array.
    {
        const float4* sh = reinterpret_cast<const float4*>(gBhi);
        const float4* sl = reinterpret_cast<const float4*>(gBlo);
        float4* dh = reinterpret_cast<float4*>(Bhi);
        float4* dl = reinterpret_cast<float4*>(Blo);
        for (int i = tid; i < (NP * KP * 2) / 16; i += NTHREADS) {
            dh[i] = __ldg(sh + i);
            dl[i] = __ldg(sl + i);
        }
    }
    if (tid < NP) sbias[tid] = (tid < Dd) ? __ldg(gb + tid) : 0.f;

    // Stage A: split fp32 [agg(100) | root(100)] into bf16 hi/lo.
    for (int idx = tid; idx < 128 * 50; idx += NTHREADS) {
        int r = idx / 50, q = idx - r * 50;
        int node = base + r;
        float4 v = make_float4(0.f, 0.f, 0.f, 0.f);
        if (node < n)
            v = (q < 25) ? __ldg(reinterpret_cast<const float4*>(
                                 agg + (size_t)node * Dd) + q)
                         : __ldg(reinterpret_cast<const float4*>(
                                 root + (size_t)node * Dd) + (q - 25));
        int kb = (q < 25) ? q * 4 : 100 + (q - 25) * 4;
        __nv_bfloat162 h01 = __floats2bfloat162_rn(v.x, v.y);
        __nv_bfloat162 h23 = __floats2bfloat162_rn(v.z, v.w);
        float2 f01 = __bfloat1622float2(h01);
        float2 f23 = __bfloat1622float2(h23);
        __nv_bfloat162 l01 = __floats2bfloat162_rn(v.x - f01.x, v.y - f01.y);
        __nv_bfloat162 l23 = __floats2bfloat162_rn(v.z - f23.x, v.w - f23.y);
        uint32_t* dh = reinterpret_cast<uint32_t*>(Ahi + r * KP + kb);
        uint32_t* dl = reinterpret_cast<uint32_t*>(Alo + r * KP + kb);
        dh[0] = *reinterpret_cast<uint32_t*>(&h01);
        dh[1] = *reinterpret_cast<uint32_t*>(&h23);
        dl[0] = *reinterpret_cast<uint32_t*>(&l01);
        dl[1] = *reinterpret_cast<uint32_t*>(&l23);
    }
    // Zero A pad cols k=200..207 (read by the last k-step).
    for (int i = tid; i < 128 * 4; i += NTHREADS) {
        int r = i >> 2, c = i & 3;
        reinterpret_cast<uint32_t*>(Ahi)[r * (KP / 2) + 100 + c] = 0u;
        reinterpret_cast<uint32_t*>(Alo)[r * (KP / 2) + 100 + c] = 0u;
    }
    __syncthreads();

    const int lane = tid & 31;
    const int m0 = (tid >> 5) * 16;

    float acc[13][4];
    #pragma unroll
    for (int t = 0; t < 13; t++)
        acc[t][0] = acc[t][1] = acc[t][2] = acc[t][3] = 0.f;

    const int arow = m0 + (lane & 15);
    const int akoff = (lane >> 4) << 3;
    const int brow = lane & 7;
    const int bkoff = ((lane >> 3) & 1) << 3;

    #pragma unroll 1
    for (int p = 0; p < 3; p++) {
        const __nv_bfloat16* As_ = (p < 2) ? Ahi : Alo;
        const __nv_bfloat16* Bs_ = (p == 1) ? Blo : Bhi;
        #pragma unroll 1
        for (int ks = 0; ks < 13; ks++) {
            int k0 = ks * 16;
            uint32_t a0, a1, a2, a3;
            {
                uint32_t addr = (uint32_t)__cvta_generic_to_shared(
                    As_ + arow * KP + k0 + akoff);
                asm volatile(
                    "ldmatrix.sync.aligned.m8n8.x4.shared.b16 {%0,%1,%2,%3}, [%4];"
                    : "=r"(a0), "=r"(a1), "=r"(a2), "=r"(a3) : "r"(addr));
            }
            #pragma unroll
            for (int nt = 0; nt < 13; nt++) {
                uint32_t b0, b1;
                uint32_t baddr = (uint32_t)__cvta_generic_to_shared(
                    Bs_ + (nt * 8 + brow) * KP + k0 + bkoff);
                asm volatile(
                    "ldmatrix.sync.aligned.m8n8.x2.shared.b16 {%0,%1}, [%2];"
                    : "=r"(b0), "=r"(b1) : "r"(baddr));
                asm volatile(
                    "mma.sync.aligned.m16n8k16.row.col.f32.bf16.bf16.f32 "
                    "{%0,%1,%2,%3}, {%4,%5,%6,%7}, {%8,%9}, {%0,%1,%2,%3};"
                    : "+f"(acc[nt][0]), "+f"(acc[nt][1]),
                      "+f"(acc[nt][2]), "+f"(acc[nt][3])
                    : "r"(a0), "r"(a1), "r"(a2), "r"(a3), "r"(b0), "r"(b1));
            }
        }
    }

    // Epilogue: bias (+ReLU), store.
    int row0 = base + m0 + (lane >> 2);
    int row1 = row0 + 8;
    #pragma unroll
    for (int nt = 0; nt < 13; nt++) {
        int col0 = nt * 8 + ((lane & 3) << 1);
        if (col0 >= Dd) continue;
        float bv0 = sbias[col0], bv1 = sbias[col0 + 1];
        float v00 = acc[nt][0] + bv0, v01 = acc[nt][1] + bv1;
        float v10 = acc[nt][2] + bv0, v11 = acc[nt][3] + bv1;
        if (doRelu) {
            v00 = fmaxf(v00, 0.f); v01 = fmaxf(v01, 0.f);
            v10 = fmaxf(v10, 0.f); v11 = fmaxf(v11, 0.f);
        }
        if (row0 < n)
            *reinterpret_cast<float2*>(out + (size_t)row0 * Dd + col0) =
                make_float2(v00, v01);
        if (row1 < n)
            *reinterpret_cast<float2*>(out + (size_t)row1 * Dd + col0) =
                make_float2(v10, v11);
    }
}

extern "C" void kernel_launch(void* const* d_in, const int* in_sizes, int n_in,
                              void* d_out, int out_size)
{
    const float* x   = (const float*)d_in[0];
    const int*   ei  = (const int*)d_in[1];
    const float* Wsa = (const float*)d_in[3];
    const float* Wsr = (const float*)d_in[4];
    const float* bs_ = (const float*)d_in[5];
    const float* Wma = (const float*)d_in[6];
    const float* Wmr = (const float*)d_in[7];
    const float* bm  = (const float*)d_in[8];
    const float* Wva = (const float*)d_in[9];
    const float* Wvr = (const float*)d_in[10];
    const float* bv  = (const float*)d_in[11];

    int n  = in_sizes[0] / Dd;
    int nE = in_sizes[1] / 2;
    const int* src  = ei;
    const int* dstp = ei + nE;

    float *agg, *feat;
    int *deg, *off, *cur, *csr, *bsum;
    __nv_bfloat16 *bhiBase, *bloBase;
    cudaGetSymbolAddress((void**)&agg,  g_agg);
    cudaGetSymbolAddress((void**)&feat, g_feat);
    cudaGetSymbolAddress((void**)&deg,  g_deg);
    cudaGetSymbolAddress((void**)&off,  g_off);
    cudaGetSymbolAddress((void**)&cur,  g_cur);
    cudaGetSymbolAddress((void**)&csr,  g_csr);
    cudaGetSymbolAddress((void**)&bsum, g_bsum);
    cudaGetSymbolAddress((void**)&bhiBase, g_Bhi);
    cudaGetSymbolAddress((void**)&bloBase, g_Blo);

    size_t smem = 512 + (size_t)(2 * 128 + 2 * NP) * KP * sizeof(__nv_bfloat16);
    static bool attrSet = false;
    if (!attrSet) {
        cudaFuncSetAttribute(layer_mma,
                             cudaFuncAttributeMaxDynamicSharedMemorySize, (int)smem);
        attrSet = true;
    }

    // --- Weight prep (bf16 hi/lo, padded+transposed) ---
    prep_kernel<<<(3 * NP * KP + 255) / 256, 256>>>(Wsa, Wsr, Wma, Wmr, Wva, Wvr);

    // --- CSR build ---
    int nb = (n + SCAN_B - 1) / SCAN_B;
    cudaMemsetAsync(deg, 0, (size_t)n * sizeof(int));
    hist_kernel<<<(nE + 255) / 256, 256>>>(dstp, deg, nE);
    scanA_kernel<<<nb, SCAN_B>>>(deg, cur, bsum, n);
    scanB_kernel<<<1, 32>>>(bsum, nb);
    scanC_kernel<<<nb, SCAN_B>>>(cur, bsum, deg, off, cur, n);
    scatter_kernel<<<(nE + 255) / 256, 256>>>(src, dstp, cur, csr, nE);

    // --- Layer 1 ---
    int gatherBlocks = (n + 7) / 8;
    gather_kernel<<<gatherBlocks, 256>>>(x, csr, off, agg, n);

    int rowBlocks = (n + 127) / 128;
    layer_mma<<<dim3(rowBlocks, 1), NTHREADS, smem>>>(
        agg, x, bhiBase, bloBase, bs_,
        bhiBase, bloBase, bs_, feat, n, 1);

    // --- Layers 2+3 (shared aggregation over feat) ---
    gather_kernel<<<gatherBlocks, 256>>>(feat, csr, off, agg, n);

    float* outp = (float*)d_out;
    layer_mma<<<dim3(rowBlocks, 2), NTHREADS, smem>>>(
        agg, feat,
        bhiBase + (size_t)1 * NP * KP, bloBase + (size_t)1 * NP * KP, bm,
        bhiBase + (size_t)2 * NP * KP, bloBase + (size_t)2 * NP * KP, bv,
        outp, n, 0);
}